// round 7
// baseline (speedup 1.0000x reference)
#include <cuda_runtime.h>
#include <math.h>
#include <stdint.h>

// ---------------------------------------------------------------------------
// PPO fused loss on GB300 — persistent 512-thread CTAs, B fragments RESIDENT
// in smem across tiles, mma.sync tf32 actor+critic, split-N partial softmax,
// blocked-scan GAE.
// ---------------------------------------------------------------------------

#define T_MAX   262144
#define S_DIM   512
#define A_DIM   64
#define BM      128
#define GAMMA_F 0.99f
#define GL_F    (0.99f * 0.98f)
#define CLIP_LO 0.8f
#define CLIP_HI 1.2f
#define ENT_C   0.01f
#define CHUNK   2048
#define NB_MAX  (T_MAX / CHUNK)
#define NGRP    9
#define GRID1   152
#define THREADS1 512

// scratch
__device__ float g_delta[T_MAX];
__device__ float g_ratio[T_MAX];
__device__ float g_ent[T_MAX / BM];
__device__ float g_cA[NB_MAX];
__device__ float g_cB[NB_MAX];
__device__ float g_surr[NB_MAX];
__device__ float g_adv2[NB_MAX];
// B fragments: [64 ksteps][9 groups][32 lanes] float2 (tf32-rounded)
__device__ __align__(16) float2 g_wfrag[64 * NGRP * 32];

// ---------------- smem layout ----------------
#define SLABS        16
#define A_ROW_F      36                     // 32 floats + 4 pad (144 B rows)
#define SLAB_BYTES   (128 * 144)            // 18432
#define STAGE_BYTES  (2 * SLAB_BYTES)       // states + next_states = 36864
#define B_BYTES      (64 * NGRP * 32 * 8)   // 147456
#define OFF_B    (2 * STAGE_BYTES)          // 73728
#define OFF_EX   (OFF_B + B_BYTES)          // 221184 : float4[128][2]
#define OFF_SNV  (OFF_EX + 4096)            // 225280 : float[128]
#define OFF_ENT  (OFF_SNV + 512)            // 225792
#define SMEM_TOTAL (OFF_ENT + 64)           // 225856

// ---------------- PTX helpers ----------------
__device__ __forceinline__ uint32_t smem_to_u32(const void* p) {
    uint32_t a;
    asm("{ .reg .u64 t; cvta.to.shared.u64 t, %1; cvt.u32.u64 %0, t; }" : "=r"(a) : "l"(p));
    return a;
}
__device__ __forceinline__ void cpa16(uint32_t dst, const void* src) {
    asm volatile("cp.async.cg.shared.global [%0], [%1], 16;" :: "r"(dst), "l"(src) : "memory");
}
#define CP_COMMIT() asm volatile("cp.async.commit_group;" ::: "memory")
#define CP_WAIT1()  asm volatile("cp.async.wait_group 1;" ::: "memory")
#define CP_WAIT0()  asm volatile("cp.async.wait_group 0;" ::: "memory")

__device__ __forceinline__ void mma_tf32(float (&d)[4], const uint32_t (&a)[4],
                                         const uint32_t (&b)[2]) {
    asm volatile(
        "mma.sync.aligned.m16n8k8.row.col.f32.tf32.tf32.f32 "
        "{%0,%1,%2,%3}, {%4,%5,%6,%7}, {%8,%9}, {%0,%1,%2,%3};"
        : "+f"(d[0]), "+f"(d[1]), "+f"(d[2]), "+f"(d[3])
        : "r"(a[0]), "r"(a[1]), "r"(a[2]), "r"(a[3]), "r"(b[0]), "r"(b[1]));
}
__device__ __forceinline__ uint32_t to_tf32(float x) {
    uint32_t r;
    asm("cvt.rna.tf32.f32 %0, %1;" : "=r"(r) : "f"(x));
    return r;
}

// ---------------------------------------------------------------------------
// prep: pack [actor_w | critic_w] into mma B-fragment order (tf32-rounded).
// ---------------------------------------------------------------------------
__global__ void kprep(const float* __restrict__ aw, const float* __restrict__ cw) {
    int e = blockIdx.x * 256 + threadIdx.x;      // 18432 entries
    int lane = e & 31, gk = e >> 5;
    int G = gk % NGRP, ks = gk / NGRP;
    int nloc = lane >> 2;
    int k = ks * 8 + (lane & 3);
    float w0, w1;
    if (G < 8) {
        int n = G * 8 + nloc;
        w0 = aw[k * A_DIM + n];
        w1 = aw[(k + 4) * A_DIM + n];
    } else {
        w0 = (nloc == 0) ? cw[k] : 0.f;
        w1 = (nloc == 0) ? cw[k + 4] : 0.f;
    }
    float2 v;
    v.x = __uint_as_float(to_tf32(w0));
    v.y = __uint_as_float(to_tf32(w1));
    g_wfrag[e] = v;
}

// ---------------------------------------------------------------------------
// slab loader: L -> (tile, s). states + next_states slabs into stage L&1.
// 2048 granules of 16B, 512 threads x 4.
// ---------------------------------------------------------------------------
__device__ __forceinline__ void issue_slab(uint32_t su, int L,
                                           const float* __restrict__ states,
                                           const float* __restrict__ next_states,
                                           int bid, int gdim, int nb1, int tid) {
    const int tile = bid + (L >> 4) * gdim;
    if (tile >= nb1) return;
    const int s = L & 15;
    const uint32_t sbase = su + (L & 1) * STAGE_BYTES;
    const size_t goff = (size_t)tile * BM * S_DIM + s * 32;
#pragma unroll
    for (int i = 0; i < 4; ++i) {
        int g = tid + i * THREADS1;            // 0..2047
        int mtx = g >> 10;
        int r = (g & 1023) >> 3, u = g & 7;
        const float* src = (mtx ? next_states : states) + goff + (size_t)r * S_DIM + u * 4;
        cpa16(sbase + mtx * SLAB_BYTES + r * 144 + u * 16, src);
    }
}

// ---------------------------------------------------------------------------
// Main fused kernel (persistent, B resident)
// ---------------------------------------------------------------------------
__global__ void __launch_bounds__(THREADS1, 1)
k1_mma(const float* __restrict__ states,
       const float* __restrict__ next_states,
       const float* __restrict__ rewards,
       const int*   __restrict__ dones,
       const int*   __restrict__ actions,
       const float* __restrict__ log_probs,
       const float* __restrict__ actor_b,
       const float* __restrict__ critic_b,
       int nb1) {
    extern __shared__ __align__(16) char smem[];
    const uint32_t su = smem_to_u32(smem);
    const int tid  = threadIdx.x;
    const int w    = tid >> 5;
    const int wa   = w & 7;                    // row block: rows 16wa..16wa+15
    const int wb   = w >> 3;                   // N half: cols 32wb..32wb+31
    const int lane = tid & 31;
    const int q = lane >> 2, j = lane & 3;
    const int bid = blockIdx.x, gdim = gridDim.x;

    float4* sx  = (float4*)(smem + OFF_EX);    // [128][2] partials
    float*  snv = (float*)(smem + OFF_SNV);
    float*  sEnt = (float*)(smem + OFF_ENT);
    const float cb = critic_b[0];

    // bias for this warp's 8 columns: col = 32wb + g*8 + j*2 + b
    float2 bias[4];
#pragma unroll
    for (int g = 0; g < 4; ++g)
        bias[g] = __ldg((const float2*)(actor_b + wb * 32 + g * 8 + j * 2));

    // stage resident B table (group 0), then prefetch 2 slabs
    {
        const char* bsrc = (const char*)g_wfrag;
#pragma unroll
        for (int i = 0; i < 18; ++i) {
            int g = tid + i * THREADS1;        // 0..9215
            cpa16(su + OFF_B + g * 16, bsrc + (size_t)g * 16);
        }
        CP_COMMIT();
    }
    issue_slab(su, 0, states, next_states, bid, gdim, nb1, tid); CP_COMMIT();
    issue_slab(su, 1, states, next_states, bid, gdim, nb1, tid); CP_COMMIT();

    const float2* Bt = (const float2*)(smem + OFF_B);

    for (int it = 0;; ++it) {
        const int tile = bid + it * gdim;
        if (tile >= nb1) break;
        const int row0 = tile * BM;

        float acc[4][4];    // this warp's 4 actor groups
        float accC[4];      // critic (wb0: values from states, wb1: next_values)
#pragma unroll
        for (int g = 0; g < 4; ++g)
#pragma unroll
            for (int p = 0; p < 4; ++p) acc[g][p] = 0.f;
#pragma unroll
        for (int p = 0; p < 4; ++p) accC[p] = 0.f;

        for (int s = 0; s < SLABS; ++s) {
            const int L = it * SLABS + s;
            CP_WAIT1();
            __syncthreads();

            const char* stage = smem + (size_t)(L & 1) * STAGE_BYTES;
            const float* Ar = (const float*)stage + (16 * wa + q) * A_ROW_F + j;
            const float* Nr = (const float*)(stage + SLAB_BYTES) + (16 * wa + q) * A_ROW_F + j;

#pragma unroll
            for (int ks = 0; ks < 4; ++ks) {
                uint32_t af[4];
                const float* Am = Ar + ks * 8;
                af[0] = __float_as_uint(Am[0]);
                af[1] = __float_as_uint(Am[8 * A_ROW_F]);
                af[2] = __float_as_uint(Am[4]);
                af[3] = __float_as_uint(Am[8 * A_ROW_F + 4]);

                const float2* Bk = Bt + (size_t)((s * 4 + ks) * NGRP) * 32 + lane;
#pragma unroll
                for (int g = 0; g < 4; ++g) {
                    uint32_t bf[2];
                    float2 v = Bk[(wb * 4 + g) * 32];
                    bf[0] = __float_as_uint(v.x);
                    bf[1] = __float_as_uint(v.y);
                    mma_tf32(acc[g], af, bf);
                }
                uint32_t bfc[2];
                {
                    float2 v = Bk[8 * 32];
                    bfc[0] = __float_as_uint(v.x);
                    bfc[1] = __float_as_uint(v.y);
                }
                if (wb) {
                    uint32_t an[4];
                    const float* Nm = Nr + ks * 8;
                    an[0] = __float_as_uint(Nm[0]);
                    an[1] = __float_as_uint(Nm[8 * A_ROW_F]);
                    an[2] = __float_as_uint(Nm[4]);
                    an[3] = __float_as_uint(Nm[8 * A_ROW_F + 4]);
                    mma_tf32(accC, an, bfc);
                } else {
                    mma_tf32(accC, af, bfc);
                }
            }
            __syncthreads();            // stage (L&1) consumed
            issue_slab(su, L + 2, states, next_states, bid, gdim, nb1, tid);
            CP_COMMIT();
        }

        // ---- split-N partial softmax epilogue ----
        float mh[2], seh[2], peh[2], ch[2], vh[2];
#pragma unroll
        for (int half = 0; half < 2; ++half) {
            float tl[4][2];
            float m = -1e30f;
#pragma unroll
            for (int g = 0; g < 4; ++g) {
                tl[g][0] = acc[g][half * 2]     + bias[g].x;
                tl[g][1] = acc[g][half * 2 + 1] + bias[g].y;
                m = fmaxf(m, fmaxf(tl[g][0], tl[g][1]));
            }
            m = fmaxf(m, __shfl_xor_sync(0xffffffffu, m, 1));
            m = fmaxf(m, __shfl_xor_sync(0xffffffffu, m, 2));

            float se = 0.f, pe = 0.f;
#pragma unroll
            for (int g = 0; g < 4; ++g) {
#pragma unroll
                for (int b = 0; b < 2; ++b) {
                    float t = tl[g][b] - m;
                    float e = __expf(t);
                    se += e;
                    pe = fmaf(e, t, pe);
                }
            }
            se += __shfl_xor_sync(0xffffffffu, se, 1);
            se += __shfl_xor_sync(0xffffffffu, se, 2);
            pe += __shfl_xor_sync(0xffffffffu, pe, 1);
            pe += __shfl_xor_sync(0xffffffffu, pe, 2);

            const int r = 16 * wa + q + half * 8;
            const int a = __ldg(actions + row0 + r);
            float cand = -1e30f;
            if ((a >> 5) == wb) {
                const int al = a & 31;
                if (j == ((al >> 1) & 3)) {
                    const int ga = al >> 3, ba = al & 1;
#pragma unroll
                    for (int g = 0; g < 4; ++g)
                        if (g == ga) cand = ba ? tl[g][1] : tl[g][0];
                }
            }
            cand = fmaxf(cand, __shfl_xor_sync(0xffffffffu, cand, 1));
            cand = fmaxf(cand, __shfl_xor_sync(0xffffffffu, cand, 2));

            mh[half] = m; seh[half] = se; peh[half] = pe; ch[half] = cand;
            vh[half] = accC[half * 2] + cb;
        }
        if (j == 0) {
#pragma unroll
            for (int half = 0; half < 2; ++half) {
                const int r = 16 * wa + q + half * 8;
                sx[r * 2 + wb] = make_float4(mh[half], seh[half], peh[half], ch[half]);
                if (wb) snv[r] = vh[half];
            }
        }
        __syncthreads();

        if (wb == 0) {
            float ent2 = 0.f;
            if (j == 0) {
#pragma unroll
                for (int half = 0; half < 2; ++half) {
                    const int r = 16 * wa + q + half * 8;
                    const int grow = row0 + r;
                    float4 o = sx[r * 2 + 1];
                    const float M  = fmaxf(mh[half], o.x);
                    const float e0 = __expf(mh[half] - M);
                    const float e1 = __expf(o.x - M);
                    const float se = seh[half] * e0 + o.y * e1;
                    const float pe = fmaf(seh[half], mh[half] - M, peh[half]) * e0
                                   + fmaf(o.y, o.x - M, o.z) * e1;
                    const float cand = fmaxf(ch[half], o.w);
                    const float logse = __logf(se);
                    const float ratio = __expf(cand - M - logse - __ldg(log_probs + grow));
                    const float nd = 1.f - (float)__ldg(dones + grow);
                    g_delta[grow] = __ldg(rewards + grow) + GAMMA_F * snv[r] * nd - vh[half];
                    g_ratio[grow] = ratio;
                    ent2 += logse - pe / se;
                }
            }
#pragma unroll
            for (int o = 16; o > 0; o >>= 1)
                ent2 += __shfl_xor_sync(0xffffffffu, ent2, o);
            if (lane == 0) sEnt[wa] = ent2;
        }
        __syncthreads();
        if (tid == 0) {
            float s8 = 0.f;
#pragma unroll
            for (int i = 0; i < 8; ++i) s8 += sEnt[i];
            g_ent[tile] = s8;
        }
    }
    CP_WAIT0();
}

// ---------------------------------------------------------------------------
// GAE scan
// ---------------------------------------------------------------------------
__device__ __forceinline__ void thread_affine(const int* __restrict__ dones,
                                              int base, float (&d)[8], float (&c)[8],
                                              float& A, float& Bv) {
    float4 d0 = *(const float4*)&g_delta[base];
    float4 d1 = *(const float4*)&g_delta[base + 4];
    int4 q0 = *(const int4*)&dones[base];
    int4 q1 = *(const int4*)&dones[base + 4];
    d[0]=d0.x; d[1]=d0.y; d[2]=d0.z; d[3]=d0.w;
    d[4]=d1.x; d[5]=d1.y; d[6]=d1.z; d[7]=d1.w;
    c[0]=GL_F*(1.f-(float)q0.x); c[1]=GL_F*(1.f-(float)q0.y);
    c[2]=GL_F*(1.f-(float)q0.z); c[3]=GL_F*(1.f-(float)q0.w);
    c[4]=GL_F*(1.f-(float)q1.x); c[5]=GL_F*(1.f-(float)q1.y);
    c[6]=GL_F*(1.f-(float)q1.z); c[7]=GL_F*(1.f-(float)q1.w);
    A = 1.f; Bv = 0.f;
#pragma unroll
    for (int jj = 7; jj >= 0; --jj) { Bv = fmaf(c[jj], Bv, d[jj]); A = c[jj] * A; }
}

__global__ void __launch_bounds__(256)
k2_chunk_reduce(const int* __restrict__ dones) {
    __shared__ float sa[256], sb[256];
    const int tid = threadIdx.x;
    const int base = blockIdx.x * CHUNK + tid * 8;
    float d[8], c[8], A, Bv;
    thread_affine(dones, base, d, c, A, Bv);
    sa[tid] = A; sb[tid] = Bv;
    __syncthreads();
    for (int s = 1; s < 256; s <<= 1) {
        if ((tid & (2 * s - 1)) == 0) {
            float al = sa[tid], bl = sb[tid];
            float ar = sa[tid + s], br = sb[tid + s];
            sa[tid] = al * ar;
            sb[tid] = fmaf(al, br, bl);
        }
        __syncthreads();
    }
    if (tid == 0) { g_cA[blockIdx.x] = sa[0]; g_cB[blockIdx.x] = sb[0]; }
}

__global__ void __launch_bounds__(256)
k4_apply(const int* __restrict__ dones, int nb) {
    __shared__ float sa[256], sb[256];
    __shared__ float ca[NB_MAX], cbv[NB_MAX];
    const int tid = threadIdx.x;

    if (tid < NB_MAX) { ca[tid] = g_cA[tid]; cbv[tid] = g_cB[tid]; }
    __syncthreads();
    for (int dd = 1; dd < NB_MAX; dd <<= 1) {
        float a = 0.f, b = 0.f, ar = 1.f, br = 0.f;
        if (tid < NB_MAX) {
            a = ca[tid]; b = cbv[tid];
            if (tid + dd < NB_MAX) { ar = ca[tid + dd]; br = cbv[tid + dd]; }
        }
        __syncthreads();
        if (tid < NB_MAX) { ca[tid] = a * ar; cbv[tid] = fmaf(a, br, b); }
        __syncthreads();
    }
    const int blk = blockIdx.x;
    const float xb = (blk + 1 < nb) ? cbv[blk + 1] : 0.f;

    const int base = blk * CHUNK + tid * 8;
    float d[8], c[8], A, Bv;
    thread_affine(dones, base, d, c, A, Bv);
    sa[tid] = A; sb[tid] = Bv;
    __syncthreads();
    for (int dd = 1; dd < 256; dd <<= 1) {
        float al = sa[tid], bl = sb[tid];
        float ar = 1.f, br = 0.f;
        if (tid + dd < 256) { ar = sa[tid + dd]; br = sb[tid + dd]; }
        __syncthreads();
        sa[tid] = al * ar;
        sb[tid] = fmaf(al, br, bl);
        __syncthreads();
    }
    float xin = (tid == 255) ? xb : fmaf(sa[tid + 1], xb, sb[tid + 1]);

    float4 r0 = *(const float4*)&g_ratio[base];
    float4 r1 = *(const float4*)&g_ratio[base + 4];
    float rt[8] = {r0.x, r0.y, r0.z, r0.w, r1.x, r1.y, r1.z, r1.w};

    float adv = xin, s1 = 0.f, s2 = 0.f;
#pragma unroll
    for (int jj = 7; jj >= 0; --jj) {
        adv = fmaf(c[jj], adv, d[jj]);
        const float r = rt[jj];
        const float rc = fminf(fmaxf(r, CLIP_LO), CLIP_HI);
        s1 += fminf(r * adv, rc * adv);
        s2 = fmaf(adv, adv, s2);
    }
    __syncthreads();
    sa[tid] = s1; sb[tid] = s2;
    __syncthreads();
    for (int s = 128; s > 0; s >>= 1) {
        if (tid < s) { sa[tid] += sa[tid + s]; sb[tid] += sb[tid + s]; }
        __syncthreads();
    }
    if (tid == 0) { g_surr[blk] = sa[0]; g_adv2[blk] = sb[0]; }
}

__global__ void __launch_bounds__(256)
k5_final(float* __restrict__ out, int T, int nb, int nb1) {
    __shared__ float se_[256], ss_[256], sv_[256];
    const int tid = threadIdx.x;
    float e = 0.f, s = 0.f, v = 0.f;
    for (int i = tid; i < nb1; i += 256) e += g_ent[i];
    for (int i = tid; i < nb; i += 256) { s += g_surr[i]; v += g_adv2[i]; }
    se_[tid] = e; ss_[tid] = s; sv_[tid] = v;
    __syncthreads();
    for (int st = 128; st > 0; st >>= 1) {
        if (tid < st) {
            se_[tid] += se_[tid + st];
            ss_[tid] += ss_[tid + st];
            sv_[tid] += sv_[tid + st];
        }
        __syncthreads();
    }
    if (tid == 0) {
        const float invT = 1.f / (float)T;
        out[0] = -(ss_[0] * invT) - ENT_C * (se_[0] * invT);
        out[1] = sv_[0] * invT;
    }
}

extern "C" void kernel_launch(void* const* d_in, const int* in_sizes, int n_in,
                              void* d_out, int out_size) {
    const float* states      = (const float*)d_in[0];
    const float* next_states = (const float*)d_in[1];
    const float* rewards     = (const float*)d_in[2];
    const int*   dones       = (const int*)  d_in[3];
    const int*   actions     = (const int*)  d_in[4];
    const float* log_probs   = (const float*)d_in[5];
    const float* actor_w     = (const float*)d_in[6];
    const float* actor_b     = (const float*)d_in[7];
    const float* critic_w    = (const float*)d_in[8];
    const float* critic_b    = (const float*)d_in[9];
    float* out = (float*)d_out;

    const int T   = in_sizes[2];
    const int nb1 = T / BM;       // 2048
    const int nb  = T / CHUNK;    // 128
    const int grid1 = nb1 < GRID1 ? nb1 : GRID1;

    cudaFuncSetAttribute(k1_mma, cudaFuncAttributeMaxDynamicSharedMemorySize, SMEM_TOTAL);

    kprep<<<(64 * NGRP * 32) / 256, 256>>>(actor_w, critic_w);
    k1_mma<<<grid1, THREADS1, SMEM_TOTAL>>>(states, next_states, rewards, dones, actions,
                                            log_probs, actor_b, critic_b, nb1);
    k2_chunk_reduce<<<nb, 256>>>(dones);
    k4_apply<<<nb, 256>>>(dones, nb);
    k5_final<<<1, 256>>>(out, T, nb, nb1);
}

// round 8
// speedup vs baseline: 1.3847x; 1.3847x over previous
#include <cuda_runtime.h>
#include <math.h>
#include <stdint.h>

// ---------------------------------------------------------------------------
// PPO fused loss on GB300 — R6 structure (mma.sync tf32, B window staged per
// slab, 2 CTAs/SM) + atomic tile scheduler + single-kernel spin-synced GAE.
// ---------------------------------------------------------------------------

#define T_MAX   262144
#define S_DIM   512
#define A_DIM   64
#define BM      128
#define GAMMA_F 0.99f
#define GL_F    (0.99f * 0.98f)
#define CLIP_LO 0.8f
#define CLIP_HI 1.2f
#define ENT_C   0.01f
#define CHUNK   2048
#define NB_MAX  (T_MAX / CHUNK)
#define NGRP    9                          // 8 actor col-groups + 1 critic group
#define GRID1   304                        // 2 CTAs x 152 SMs

// scratch
__device__ float g_delta[T_MAX];
__device__ float g_ratio[T_MAX];
__device__ float g_ent[T_MAX / BM];
__device__ float g_cA[NB_MAX];
__device__ float g_cB[NB_MAX];
__device__ float g_surr[NB_MAX];
__device__ float g_adv2[NB_MAX];
__device__ int   g_tile;                   // k1 dynamic tile counter
__device__ int   g_flag;                   // kgae phase-1 publish count
__device__ int   g_flag2;                  // kgae phase-2 done count
// B fragments: [64 ksteps][9 groups][32 lanes] float2 (tf32-rounded)
__device__ __align__(16) float2 g_wfrag[64 * NGRP * 32];

// ---------------- smem layout ----------------
#define SLABS        16
#define A_ROW_F      36                     // 32 floats + 4 pad (144 B rows)
#define SLAB_BYTES   (128 * 144)            // 18432
#define BW_BYTES     (4 * NGRP * 32 * 8)    // per-slab B window = 9216
#define STAGE_BYTES  (2 * SLAB_BYTES + BW_BYTES)   // 46080
#define OFF_ENT   (2 * STAGE_BYTES)         // 92160
#define OFF_NXT   (OFF_ENT + 64)            // 92224
#define SMEM_TOTAL (OFF_NXT + 16)           // 92240 (x2 CTAs <= 227KB)

// ---------------- PTX helpers ----------------
__device__ __forceinline__ uint32_t smem_to_u32(const void* p) {
    uint32_t a;
    asm("{ .reg .u64 t; cvta.to.shared.u64 t, %1; cvt.u32.u64 %0, t; }" : "=r"(a) : "l"(p));
    return a;
}
__device__ __forceinline__ void cpa16(uint32_t dst, const void* src) {
    asm volatile("cp.async.cg.shared.global [%0], [%1], 16;" :: "r"(dst), "l"(src) : "memory");
}
#define CP_COMMIT() asm volatile("cp.async.commit_group;" ::: "memory")
#define CP_WAIT1()  asm volatile("cp.async.wait_group 1;" ::: "memory")
#define CP_WAIT0()  asm volatile("cp.async.wait_group 0;" ::: "memory")

__device__ __forceinline__ void mma_tf32(float (&d)[4], const uint32_t (&a)[4],
                                         const uint32_t (&b)[2]) {
    asm volatile(
        "mma.sync.aligned.m16n8k8.row.col.f32.tf32.tf32.f32 "
        "{%0,%1,%2,%3}, {%4,%5,%6,%7}, {%8,%9}, {%0,%1,%2,%3};"
        : "+f"(d[0]), "+f"(d[1]), "+f"(d[2]), "+f"(d[3])
        : "r"(a[0]), "r"(a[1]), "r"(a[2]), "r"(a[3]), "r"(b[0]), "r"(b[1]));
}
__device__ __forceinline__ uint32_t to_tf32(float x) {
    uint32_t r;
    asm("cvt.rna.tf32.f32 %0, %1;" : "=r"(r) : "f"(x));
    return r;
}

// ---------------------------------------------------------------------------
// prep: pack [actor_w | critic_w] into mma B-fragment order + reset counters.
// ---------------------------------------------------------------------------
__global__ void kprep(const float* __restrict__ aw, const float* __restrict__ cw) {
    if (blockIdx.x == 0 && threadIdx.x == 0) { g_tile = 0; g_flag = 0; g_flag2 = 0; }
    int e = blockIdx.x * 256 + threadIdx.x;      // 18432 entries
    int lane = e & 31, gk = e >> 5;
    int G = gk % NGRP, ks = gk / NGRP;
    int nloc = lane >> 2;
    int k = ks * 8 + (lane & 3);
    float w0, w1;
    if (G < 8) {
        int n = G * 8 + nloc;
        w0 = aw[k * A_DIM + n];
        w1 = aw[(k + 4) * A_DIM + n];
    } else {
        w0 = (nloc == 0) ? cw[k] : 0.f;
        w1 = (nloc == 0) ? cw[k + 4] : 0.f;
    }
    float2 v;
    v.x = __uint_as_float(to_tf32(w0));
    v.y = __uint_as_float(to_tf32(w1));
    g_wfrag[e] = v;
}

// ---------------------------------------------------------------------------
// slab loader: states + next_states slab (tile, s) + per-slab B window -> buf
// ---------------------------------------------------------------------------
__device__ __forceinline__ void issue_slab(uint32_t su, int buf, int tile, int s,
                                           const float* __restrict__ states,
                                           const float* __restrict__ next_states,
                                           int nb1, int tid) {
    if (tile >= nb1) return;
    const uint32_t sbase = su + buf * STAGE_BYTES;
    const size_t goff = (size_t)tile * BM * S_DIM + s * 32;
#pragma unroll
    for (int i = 0; i < 8; ++i) {
        int g = tid + i * 256;                 // 0..2047
        int mtx = g >> 10;                     // 0: states, 1: next_states
        int r = (g & 1023) >> 3, u = g & 7;
        const float* src = (mtx ? next_states : states) + goff + (size_t)r * S_DIM + u * 4;
        cpa16(sbase + mtx * SLAB_BYTES + r * 144 + u * 16, src);
    }
    // B window: 9216 B = 576 granules
    const char* bsrc = (const char*)(g_wfrag + (size_t)s * 4 * NGRP * 32);
    {
        int g = tid;
        cpa16(sbase + 2 * SLAB_BYTES + g * 16, bsrc + (size_t)g * 16);
        g = tid + 256;
        cpa16(sbase + 2 * SLAB_BYTES + g * 16, bsrc + (size_t)g * 16);
        if (tid < 64) {
            g = tid + 512;
            cpa16(sbase + 2 * SLAB_BYTES + g * 16, bsrc + (size_t)g * 16);
        }
    }
}

// ---------------------------------------------------------------------------
// Main fused kernel (persistent, dynamic tiles, depth-1 ring x 2 CTAs/SM)
// ---------------------------------------------------------------------------
__global__ void __launch_bounds__(256, 2)
k1_mma(const float* __restrict__ states,
       const float* __restrict__ next_states,
       const float* __restrict__ rewards,
       const int*   __restrict__ dones,
       const int*   __restrict__ actions,
       const float* __restrict__ log_probs,
       const float* __restrict__ actor_b,
       const float* __restrict__ critic_b,
       int nb1) {
    extern __shared__ __align__(16) char smem[];
    const uint32_t su = smem_to_u32(smem);
    const int tid  = threadIdx.x;
    const int w    = tid >> 5;                 // warp 0..7 -> rows 16w..16w+15
    const int lane = tid & 31;
    const int q = lane >> 2, j = lane & 3;

    float* sEnt = (float*)(smem + OFF_ENT);
    int*   sNxt = (int*)(smem + OFF_NXT);
    const float cb = critic_b[0];

    // bias for this thread's 16 actor columns: col = g*8 + j*2 + b
    float2 bias[8];
#pragma unroll
    for (int g = 0; g < 8; ++g)
        bias[g] = __ldg((const float2*)(actor_b + g * 8 + j * 2));

    // grab first tile, prefetch its first 2 slabs
    if (tid == 0) sNxt[1] = atomicAdd(&g_tile, 1);
    __syncthreads();
    int cur = sNxt[1];
    issue_slab(su, 0, cur, 0, states, next_states, nb1, tid); CP_COMMIT();
    issue_slab(su, 1, cur, 1, states, next_states, nb1, tid); CP_COMMIT();

    int par = 0;   // stage parity of the slab about to be consumed

    while (cur < nb1) {
        const int row0 = cur * BM;

        float acc[8][4];     // actor groups
        float accV[4], accN[4];
#pragma unroll
        for (int g = 0; g < 8; ++g)
#pragma unroll
            for (int p = 0; p < 4; ++p) acc[g][p] = 0.f;
#pragma unroll
        for (int p = 0; p < 4; ++p) { accV[p] = 0.f; accN[p] = 0.f; }

        for (int s = 0; s < SLABS; ++s) {
            CP_WAIT1();
            __syncthreads();
            if (s == 0 && tid == 0) sNxt[0] = atomicAdd(&g_tile, 1);

            const char* stage = smem + (size_t)par * STAGE_BYTES;
            const float* Ar = (const float*)stage + (16 * w + q) * A_ROW_F + j;
            const float* Nr = (const float*)(stage + SLAB_BYTES) + (16 * w + q) * A_ROW_F + j;
            const float2* Bw = (const float2*)(stage + 2 * SLAB_BYTES);

#pragma unroll
            for (int ks = 0; ks < 4; ++ks) {
                uint32_t af[4], an[4];
                const float* Am = Ar + ks * 8;
                af[0] = __float_as_uint(Am[0]);
                af[1] = __float_as_uint(Am[8 * A_ROW_F]);
                af[2] = __float_as_uint(Am[4]);
                af[3] = __float_as_uint(Am[8 * A_ROW_F + 4]);
                const float* Nm = Nr + ks * 8;
                an[0] = __float_as_uint(Nm[0]);
                an[1] = __float_as_uint(Nm[8 * A_ROW_F]);
                an[2] = __float_as_uint(Nm[4]);
                an[3] = __float_as_uint(Nm[8 * A_ROW_F + 4]);

                const float2* Bk = Bw + (size_t)ks * NGRP * 32 + lane;
                uint32_t bfc[2];
                {
                    float2 v = Bk[8 * 32];
                    bfc[0] = __float_as_uint(v.x);
                    bfc[1] = __float_as_uint(v.y);
                }
#pragma unroll
                for (int g = 0; g < 8; ++g) {
                    uint32_t bf[2];
                    float2 v = Bk[g * 32];
                    bf[0] = __float_as_uint(v.x);
                    bf[1] = __float_as_uint(v.y);
                    mma_tf32(acc[g], af, bf);
                }
                mma_tf32(accV, af, bfc);   // values
                mma_tf32(accN, an, bfc);   // next_values
            }
            __syncthreads();            // stage fully consumed; sNxt[0] visible
            // refill: slab s+2 (crosses into next tile at s=14,15)
            const int t2 = (s <= 13) ? cur : sNxt[0];
            issue_slab(su, par, t2, (s + 2) & 15, states, next_states, nb1, tid);
            CP_COMMIT();
            par ^= 1;
        }

        // ---- register epilogue: rows 16w+q (half 0) and 16w+q+8 (half 1) ----
        float ent2 = 0.f;
#pragma unroll
        for (int half = 0; half < 2; ++half) {
            float tl[8][2];
            float m = -1e30f;
#pragma unroll
            for (int g = 0; g < 8; ++g) {
                tl[g][0] = acc[g][half * 2]     + bias[g].x;
                tl[g][1] = acc[g][half * 2 + 1] + bias[g].y;
                m = fmaxf(m, fmaxf(tl[g][0], tl[g][1]));
            }
            m = fmaxf(m, __shfl_xor_sync(0xffffffffu, m, 1));
            m = fmaxf(m, __shfl_xor_sync(0xffffffffu, m, 2));

            float se = 0.f, pe = 0.f;
#pragma unroll
            for (int g = 0; g < 8; ++g) {
#pragma unroll
                for (int b = 0; b < 2; ++b) {
                    float t = tl[g][b] - m;
                    tl[g][b] = t;
                    float e = __expf(t);
                    se += e;
                    pe = fmaf(e, t, pe);
                }
            }
            se += __shfl_xor_sync(0xffffffffu, se, 1);
            se += __shfl_xor_sync(0xffffffffu, se, 2);
            pe += __shfl_xor_sync(0xffffffffu, pe, 1);
            pe += __shfl_xor_sync(0xffffffffu, pe, 2);

            const int r = 16 * w + q + half * 8;
            const int grow = row0 + r;
            const int a = __ldg(actions + grow);
            float cand = -1e30f;
            if (j == ((a >> 1) & 3)) {
                const int ga = a >> 3, ba = a & 1;
#pragma unroll
                for (int g = 0; g < 8; ++g)
                    if (g == ga) cand = ba ? tl[g][1] : tl[g][0];
            }
            cand = fmaxf(cand, __shfl_xor_sync(0xffffffffu, cand, 1));
            cand = fmaxf(cand, __shfl_xor_sync(0xffffffffu, cand, 2));

            if (j == 0) {
                const float logse = __logf(se);
                const float ratio = __expf(cand - logse - __ldg(log_probs + grow));
                const float nd = 1.f - (float)__ldg(dones + grow);
                const float v  = accV[half * 2] + cb;
                const float nv = accN[half * 2] + cb;
                g_delta[grow] = __ldg(rewards + grow) + GAMMA_F * nv * nd - v;
                g_ratio[grow] = ratio;
                ent2 += logse - pe / se;
            }
        }
#pragma unroll
        for (int o = 16; o > 0; o >>= 1) ent2 += __shfl_xor_sync(0xffffffffu, ent2, o);
        if (lane == 0) sEnt[w] = ent2;
        __syncthreads();
        if (tid == 0) {
            float s8 = 0.f;
#pragma unroll
            for (int i = 0; i < 8; ++i) s8 += sEnt[i];
            g_ent[cur] = s8;
        }
        cur = sNxt[0];       // written at s==0, stable since
    }
    CP_WAIT0();
}

// ---------------------------------------------------------------------------
// Single-kernel GAE: per-chunk suffix scan, spin-synced composite exchange,
// application, and last-block final reduction.
// ---------------------------------------------------------------------------
__device__ __forceinline__ void thread_affine(const int* __restrict__ dones,
                                              int base, float (&d)[8], float (&c)[8],
                                              float& A, float& Bv) {
    float4 d0 = *(const float4*)&g_delta[base];
    float4 d1 = *(const float4*)&g_delta[base + 4];
    int4 q0 = *(const int4*)&dones[base];
    int4 q1 = *(const int4*)&dones[base + 4];
    d[0]=d0.x; d[1]=d0.y; d[2]=d0.z; d[3]=d0.w;
    d[4]=d1.x; d[5]=d1.y; d[6]=d1.z; d[7]=d1.w;
    c[0]=GL_F*(1.f-(float)q0.x); c[1]=GL_F*(1.f-(float)q0.y);
    c[2]=GL_F*(1.f-(float)q0.z); c[3]=GL_F*(1.f-(float)q0.w);
    c[4]=GL_F*(1.f-(float)q1.x); c[5]=GL_F*(1.f-(float)q1.y);
    c[6]=GL_F*(1.f-(float)q1.z); c[7]=GL_F*(1.f-(float)q1.w);
    A = 1.f; Bv = 0.f;
#pragma unroll
    for (int jj = 7; jj >= 0; --jj) { Bv = fmaf(c[jj], Bv, d[jj]); A = c[jj] * A; }
}

__global__ void __launch_bounds__(256)
kgae(const int* __restrict__ dones, int nb, float* __restrict__ out, int T, int nb1) {
    __shared__ float sa[256], sb[256];
    __shared__ float ca[NB_MAX], cbv[NB_MAX];
    __shared__ float sv_[256];
    __shared__ int sdone;
    const int tid = threadIdx.x;
    const int blk = blockIdx.x;
    const int base = blk * CHUNK + tid * 8;

    float d[8], c[8], A, Bv;
    thread_affine(dones, base, d, c, A, Bv);

    // inclusive suffix scan over thread composites
    sa[tid] = A; sb[tid] = Bv;
    __syncthreads();
    for (int dd = 1; dd < 256; dd <<= 1) {
        float al = sa[tid], bl = sb[tid];
        float ar = 1.f, br = 0.f;
        if (tid + dd < 256) { ar = sa[tid + dd]; br = sb[tid + dd]; }
        __syncthreads();
        sa[tid] = al * ar;
        sb[tid] = fmaf(al, br, bl);
        __syncthreads();
    }

    // publish chunk composite (= suffix at tid 0), then device-wide spin sync
    if (tid == 0) {
        g_cA[blk] = sa[0];
        g_cB[blk] = sb[0];
        __threadfence();
        atomicAdd(&g_flag, 1);
        while (*(volatile int*)&g_flag < nb) { }
    }
    __syncthreads();
    __threadfence();

    // suffix scan over chunk composites
    if (tid < NB_MAX) { ca[tid] = g_cA[tid]; cbv[tid] = g_cB[tid]; }
    __syncthreads();
    for (int dd = 1; dd < NB_MAX; dd <<= 1) {
        float a = 0.f, b = 0.f, ar = 1.f, br = 0.f;
        if (tid < NB_MAX) {
            a = ca[tid]; b = cbv[tid];
            if (tid + dd < NB_MAX) { ar = ca[tid + dd]; br = cbv[tid + dd]; }
        }
        __syncthreads();
        if (tid < NB_MAX) { ca[tid] = a * ar; cbv[tid] = fmaf(a, br, b); }
        __syncthreads();
    }
    const float xb = (blk + 1 < nb) ? cbv[blk + 1] : 0.f;
    float xin = (tid == 255) ? xb : fmaf(sa[tid + 1], xb, sb[tid + 1]);

    float4 r0 = *(const float4*)&g_ratio[base];
    float4 r1 = *(const float4*)&g_ratio[base + 4];
    float rt[8] = {r0.x, r0.y, r0.z, r0.w, r1.x, r1.y, r1.z, r1.w};

    float adv = xin, s1 = 0.f, s2 = 0.f;
#pragma unroll
    for (int jj = 7; jj >= 0; --jj) {
        adv = fmaf(c[jj], adv, d[jj]);
        const float r = rt[jj];
        const float rc = fminf(fmaxf(r, CLIP_LO), CLIP_HI);
        s1 += fminf(r * adv, rc * adv);
        s2 = fmaf(adv, adv, s2);
    }
    __syncthreads();
    sa[tid] = s1; sb[tid] = s2;
    __syncthreads();
    for (int s = 128; s > 0; s >>= 1) {
        if (tid < s) { sa[tid] += sa[tid + s]; sb[tid] += sb[tid + s]; }
        __syncthreads();
    }
    if (tid == 0) {
        g_surr[blk] = sa[0];
        g_adv2[blk] = sb[0];
        __threadfence();
        sdone = atomicAdd(&g_flag2, 1);
    }
    __syncthreads();

    // last finished block reduces everything
    if (sdone == nb - 1) {
        __threadfence();
        float e = 0.f, s = 0.f, v = 0.f;
        for (int i = tid; i < nb1; i += 256) e += g_ent[i];
        for (int i = tid; i < nb; i += 256) { s += g_surr[i]; v += g_adv2[i]; }
        __syncthreads();
        sa[tid] = e; sb[tid] = s; sv_[tid] = v;
        __syncthreads();
        for (int st = 128; st > 0; st >>= 1) {
            if (tid < st) {
                sa[tid] += sa[tid + st];
                sb[tid] += sb[tid + st];
                sv_[tid] += sv_[tid + st];
            }
            __syncthreads();
        }
        if (tid == 0) {
            const float invT = 1.f / (float)T;
            out[0] = -(sb[0] * invT) - ENT_C * (sa[0] * invT);
            out[1] = sv_[0] * invT;
        }
    }
}

extern "C" void kernel_launch(void* const* d_in, const int* in_sizes, int n_in,
                              void* d_out, int out_size) {
    const float* states      = (const float*)d_in[0];
    const float* next_states = (const float*)d_in[1];
    const float* rewards     = (const float*)d_in[2];
    const int*   dones       = (const int*)  d_in[3];
    const int*   actions     = (const int*)  d_in[4];
    const float* log_probs   = (const float*)d_in[5];
    const float* actor_w     = (const float*)d_in[6];
    const float* actor_b     = (const float*)d_in[7];
    const float* critic_w    = (const float*)d_in[8];
    const float* critic_b    = (const float*)d_in[9];
    float* out = (float*)d_out;

    const int T   = in_sizes[2];
    const int nb1 = T / BM;       // 2048
    const int nb  = T / CHUNK;    // 128
    const int grid1 = nb1 < GRID1 ? nb1 : GRID1;

    cudaFuncSetAttribute(k1_mma, cudaFuncAttributeMaxDynamicSharedMemorySize, SMEM_TOTAL);

    kprep<<<(64 * NGRP * 32) / 256, 256>>>(actor_w, critic_w);
    k1_mma<<<grid1, 256, SMEM_TOTAL>>>(states, next_states, rewards, dones, actions,
                                       log_probs, actor_b, critic_b, nb1);
    kgae<<<nb, 256>>>(dones, nb, out, T, nb1);
}